// round 1
// baseline (speedup 1.0000x reference)
#include <cuda_runtime.h>

#define BB 8
#define HH 256
#define WW 256
#define NPIX (BB*HH*WW)   // per-channel element count for BN stats

// ---------------- device scratch (no allocations allowed) ----------------
__device__ float g_y1[BB*32*HH*WW];            // raw conv1 output (67 MB)
__device__ float g_y2[(size_t)BB*64*HH*WW];    // raw conv2 output (134 MB)
__device__ float g_stats[2*(32+64+128)];       // layer1 @0 (64), layer2 @64 (128), layer3 @192 (256)
__device__ float g_aff[2*(32+64+128)];         // per-layer (scale[C], shift[C]) at same offsets
__device__ float g_gath[BB*128];               // raw conv3 values at the 8 gather pixels

__global__ void zero_stats() {
    int i = blockIdx.x*blockDim.x + threadIdx.x;
    if (i < 448) g_stats[i] = 0.f;
}

// ---------------- fused conv3x3 + (optional input BN/lrelu) + stats ----------------
// Block: 256 threads, output tile 32(W) x 16(H), 16 output channels.
// Each thread: 2 adjacent output columns x 16 couts = 32 fp32 accumulators.
template<int CIN, int COUT, bool APPLY_IN, bool WRITE_OUT, bool GATHER>
__global__ __launch_bounds__(256)
void conv3x3(const float* __restrict__ in,     // [B,CIN,H,W] raw (pre-affine if APPLY_IN)
             const float* __restrict__ w,      // [COUT,CIN,3,3]
             const float* __restrict__ bias,   // [COUT]
             const float* __restrict__ aff,    // [2*CIN]: scale, shift (input transform)
             float* __restrict__ out,          // [B,COUT,H,W] raw conv output
             float* __restrict__ stats,        // [2*COUT]: sum, sumsq (atomic)
             float* __restrict__ gath,         // [B*COUT] raw values at gather pixel
             const int* __restrict__ nxy)      // int32 [B,32,2]
{
    __shared__ float s_in[18][35];     // 18 rows x 34 cols used; stride 35 -> conflict-free
    __shared__ float s_w[16*9];
    __shared__ float s_red[2][16][8];

    const int tid = threadIdx.x;
    const int tx = tid & 15, ty = tid >> 4;          // tx: 16 col-pairs, ty: 16 rows
    const int tileX = blockIdx.x * 32, tileY = blockIdx.y * 16;
    const int ng  = COUT / 16;
    const int cog = blockIdx.z % ng;
    const int b   = blockIdx.z / ng;
    const int co0 = cog * 16;

    float acc0[16], acc1[16];
    #pragma unroll
    for (int o = 0; o < 16; ++o) { acc0[o] = 0.f; acc1[o] = 0.f; }

    for (int ci = 0; ci < CIN; ++ci) {
        const float* inp = in + ((size_t)(b*CIN + ci))*HH*WW;
        // ---- load 18x34 input tile (with halo), applying BN affine + lrelu if needed
        #pragma unroll
        for (int e = tid; e < 18*34; e += 256) {
            int r = e / 34, c = e - r*34;
            int gy = tileY + r - 1, gx = tileX + c - 1;
            float v = 0.f;
            if ((unsigned)gy < (unsigned)HH && (unsigned)gx < (unsigned)WW) {
                v = inp[gy*WW + gx];
                if (APPLY_IN) {
                    v = fmaf(aff[ci], v, aff[CIN + ci]);
                    v = (v > 0.f) ? v : 0.01f*v;
                }
            }
            s_in[r][c] = v;
        }
        // ---- load 16 couts x 9 weights for this cin
        if (tid < 144) {
            int o = tid / 9, k = tid - o*9;
            s_w[tid] = w[((co0 + o)*CIN + ci)*9 + k];
        }
        __syncthreads();

        // ---- register window: 3 rows x 4 cols covers both output pixels
        float win[3][4];
        #pragma unroll
        for (int r = 0; r < 3; ++r)
            #pragma unroll
            for (int c = 0; c < 4; ++c)
                win[r][c] = s_in[ty + r][2*tx + c];

        #pragma unroll
        for (int o = 0; o < 16; ++o) {
            #pragma unroll
            for (int r = 0; r < 3; ++r)
                #pragma unroll
                for (int c = 0; c < 3; ++c) {
                    float wv = s_w[o*9 + r*3 + c];
                    acc0[o] = fmaf(wv, win[r][c],     acc0[o]);
                    acc1[o] = fmaf(wv, win[r][c + 1], acc1[o]);
                }
        }
        __syncthreads();
    }

    // ---- add bias (raw conv output, pre-BN)
    #pragma unroll
    for (int o = 0; o < 16; ++o) {
        float bv = bias[co0 + o];
        acc0[o] += bv; acc1[o] += bv;
    }

    const int y  = tileY + ty;
    const int x0 = tileX + 2*tx;

    if (WRITE_OUT) {
        #pragma unroll
        for (int o = 0; o < 16; ++o) {
            float2 v = make_float2(acc0[o], acc1[o]);
            *reinterpret_cast<float2*>(
                &out[(((size_t)b*COUT + co0 + o)*HH + y)*WW + x0]) = v;
        }
    }

    if (GATHER) {
        const int ny = nxy[b*64 + 62];   // [:, -1, 0] -> H index
        const int nx = nxy[b*64 + 63];   // [:, -1, 1] -> W index
        if (y == ny && (x0 == nx || x0 + 1 == nx)) {
            const bool first = (x0 == nx);
            #pragma unroll
            for (int o = 0; o < 16; ++o)
                gath[b*COUT + co0 + o] = first ? acc0[o] : acc1[o];
        }
    }

    // ---- block-level BN statistics, then one atomicAdd per channel
    const int lane = tid & 31, wid = tid >> 5;
    #pragma unroll
    for (int o = 0; o < 16; ++o) {
        float s  = acc0[o] + acc1[o];
        float ss = acc0[o]*acc0[o] + acc1[o]*acc1[o];
        #pragma unroll
        for (int off = 16; off; off >>= 1) {
            s  += __shfl_down_sync(0xffffffffu, s,  off);
            ss += __shfl_down_sync(0xffffffffu, ss, off);
        }
        if (lane == 0) { s_red[0][o][wid] = s; s_red[1][o][wid] = ss; }
    }
    __syncthreads();
    if (tid < 16) {
        float s = 0.f, ss = 0.f;
        #pragma unroll
        for (int k = 0; k < 8; ++k) { s += s_red[0][tid][k]; ss += s_red[1][tid][k]; }
        atomicAdd(&stats[co0 + tid],        s);
        atomicAdd(&stats[COUT + co0 + tid], ss);
    }
}

// ---------------- per-layer BN finalize: stats -> (scale, shift) ----------------
__global__ void finalize_aff(int C, int off,
                             const float* __restrict__ gamma,
                             const float* __restrict__ beta)
{
    int c = threadIdx.x;
    if (c < C) {
        const float n = (float)NPIX;
        float m = g_stats[off + c] / n;
        float v = g_stats[off + C + c] / n - m*m;
        float a = gamma[c] * rsqrtf(v + 1e-5f);
        g_aff[off + c]     = a;
        g_aff[off + C + c] = beta[c] - m*a;
    }
}

// ---------------- tail: image patches + encoded feature normalization ----------------
__global__ void tail_kernel(const float* __restrict__ image,
                            const int* __restrict__ axy,
                            const int* __restrict__ pxy,
                            const int* __restrict__ nxy,
                            float* __restrict__ out)
{
    int i = blockIdx.x*blockDim.x + threadIdx.x;
    if (i < 3528) {
        // anchor/positive/negative 7x7 patches from the raw image
        int which = i / 1176;
        int rem   = i % 1176;
        int b  = rem / 147;
        int r2 = rem % 147;
        int c  = r2 / 49;
        int p  = r2 % 49;
        int pi = p / 7, pj = p % 7;
        const int* xy = (which == 0) ? axy : (which == 1) ? pxy : nxy;
        int y0 = xy[b*64 + 62] - 3;
        int x0 = xy[b*64 + 63] - 3;
        out[i] = image[((b*3 + c)*HH + (y0 + pi))*WW + (x0 + pj)];
    } else if (i < 3528 + 1024) {
        // encoded_anchor_patches: BN affine + lrelu of gathered raw conv3 values
        int j = i - 3528;
        int c = j & 127;
        float v = fmaf(g_aff[192 + c], g_gath[j], g_aff[192 + 128 + c]);
        out[i] = (v > 0.f) ? v : 0.01f*v;
    }
}

// ---------------- launch ----------------
extern "C" void kernel_launch(void* const* d_in, const int* in_sizes, int n_in,
                              void* d_out, int out_size)
{
    const float* image = (const float*)d_in[0];
    const int*   axy   = (const int*)  d_in[1];
    const int*   pxy   = (const int*)  d_in[2];
    const int*   nxy   = (const int*)  d_in[3];
    const float* w1 = (const float*)d_in[4];
    const float* b1 = (const float*)d_in[5];
    const float* g1 = (const float*)d_in[6];
    const float* e1 = (const float*)d_in[7];
    const float* w2 = (const float*)d_in[8];
    const float* b2 = (const float*)d_in[9];
    const float* g2 = (const float*)d_in[10];
    const float* e2 = (const float*)d_in[11];
    const float* w3 = (const float*)d_in[12];
    const float* b3 = (const float*)d_in[13];
    const float* g3 = (const float*)d_in[14];
    const float* e3 = (const float*)d_in[15];
    float* outp = (float*)d_out;

    float *y1, *y2, *stats, *aff, *gath;
    cudaGetSymbolAddress((void**)&y1,    g_y1);
    cudaGetSymbolAddress((void**)&y2,    g_y2);
    cudaGetSymbolAddress((void**)&stats, g_stats);
    cudaGetSymbolAddress((void**)&aff,   g_aff);
    cudaGetSymbolAddress((void**)&gath,  g_gath);

    dim3 blk(256);

    zero_stats<<<2, 256>>>();

    // layer 1: image (no input transform) -> raw y1 + stats
    conv3x3<3, 32, false, true, false><<<dim3(8,16,BB*2), blk>>>(
        image, w1, b1, nullptr, y1, stats + 0, nullptr, nullptr);
    finalize_aff<<<1, 32>>>(32, 0, g1, e1);

    // layer 2: BN(y1)+lrelu applied on load -> raw y2 + stats
    conv3x3<32, 64, true, true, false><<<dim3(8,16,BB*4), blk>>>(
        y1, w2, b2, aff + 0, y2, stats + 64, nullptr, nullptr);
    finalize_aff<<<1, 64>>>(64, 64, g2, e2);

    // layer 3: BN(y2)+lrelu on load -> stats + 8 gathered pixels only (no store)
    conv3x3<64, 128, true, false, true><<<dim3(8,16,BB*8), blk>>>(
        y2, w3, b3, aff + 64, nullptr, stats + 192, gath, nxy);
    finalize_aff<<<1, 128>>>(128, 192, g3, e3);

    // patches + encoded output
    tail_kernel<<<(3528 + 1024 + 255)/256, 256>>>(image, axy, pxy, nxy, outp);
}

// round 2
// speedup vs baseline: 1.3504x; 1.3504x over previous
#include <cuda_runtime.h>

#define BB 8
#define HH 256
#define WW 256
#define NPIX (BB*HH*WW)   // per-channel element count for BN stats

// ---------------- device scratch (no allocations allowed) ----------------
__device__ float g_y1[BB*32*HH*WW];            // raw conv1 output (67 MB)
__device__ float g_y2[(size_t)BB*64*HH*WW];    // raw conv2 output (134 MB)
__device__ float g_stats[2*(32+64+128)];       // layer1 @0, layer2 @64, layer3 @192
__device__ float g_aff[2*(32+64+128)];
__device__ float g_gath[BB*128];

__global__ void zero_stats() {
    int i = blockIdx.x*blockDim.x + threadIdx.x;
    if (i < 448) g_stats[i] = 0.f;
}

// ---------------- fused conv3x3 + (optional input BN/lrelu) + stats ----------------
// Block: 256 threads, output tile 32(W) x 16(H), 16 output channels.
// Each thread: 2 adjacent output columns x 16 couts = 32 fp32 accumulators.
// Weights preloaded transposed [cin][k][16], input tile double-buffered.
template<int CIN, int COUT, bool APPLY_IN, bool WRITE_OUT, bool GATHER>
__global__ __launch_bounds__(256)
void conv3x3(const float* __restrict__ in,
             const float* __restrict__ w,      // [COUT,CIN,3,3]
             const float* __restrict__ bias,
             const float* __restrict__ aff,    // [2*CIN]: scale, shift (input transform)
             float* __restrict__ out,
             float* __restrict__ stats,        // [2*COUT] sum, sumsq (atomic)
             float* __restrict__ gath,
             const int* __restrict__ nxy)
{
    __shared__ __align__(16) float s_w[CIN*9*16];      // [ci][k][o]
    __shared__ __align__(16) float s_in[2][18][36];    // double-buffered halo tile
    __shared__ float s_red[2][16][8];

    const int tid = threadIdx.x;
    const int tx = tid & 15, ty = tid >> 4;
    const int tileX = blockIdx.x * 32, tileY = blockIdx.y * 16;
    const int ng  = COUT / 16;
    const int cog = blockIdx.z % ng;
    const int b   = blockIdx.z / ng;
    const int co0 = cog * 16;

    // ---- preload ALL weights, transposed to [ci][k][o] for vector broadcast reads
    for (int e = tid; e < CIN*144; e += 256) {
        int ci  = e / 144;
        int rem = e - ci*144;
        int o   = rem / 9;
        int k   = rem - o*9;
        s_w[(ci*9 + k)*16 + o] = w[((co0 + o)*CIN + ci)*9 + k];
    }

    // ---- tile loader (applies input BN affine + lrelu when APPLY_IN)
    auto load_tile = [&](int ci, int buf) {
        const float* inp = in + ((size_t)(b*CIN + ci))*HH*WW;
        const float sA = APPLY_IN ? aff[ci]       : 0.f;
        const float sB = APPLY_IN ? aff[CIN + ci] : 0.f;
        #pragma unroll
        for (int e = tid; e < 18*34; e += 256) {
            int r = e / 34, c = e - r*34;
            int gy = tileY + r - 1, gx = tileX + c - 1;
            float v = 0.f;
            if ((unsigned)gy < (unsigned)HH && (unsigned)gx < (unsigned)WW) {
                v = inp[gy*WW + gx];
                if (APPLY_IN) {
                    v = fmaf(sA, v, sB);
                    v = (v > 0.f) ? v : 0.01f*v;
                }
            }
            s_in[buf][r][c] = v;
        }
    };

    float acc0[16], acc1[16];
    #pragma unroll
    for (int o = 0; o < 16; ++o) { acc0[o] = 0.f; acc1[o] = 0.f; }

    load_tile(0, 0);
    __syncthreads();

    for (int ci = 0; ci < CIN; ++ci) {
        const int buf = ci & 1;
        // prefetch next tile into the other buffer (overlaps with compute)
        if (ci + 1 < CIN) load_tile(ci + 1, buf ^ 1);

        // ---- window: 3 rows x 4 cols via aligned LDS.64 (even element index, stride 36)
        float win[3][4];
        #pragma unroll
        for (int r = 0; r < 3; ++r) {
            float2 a = *reinterpret_cast<const float2*>(&s_in[buf][ty + r][2*tx]);
            float2 bq= *reinterpret_cast<const float2*>(&s_in[buf][ty + r][2*tx + 2]);
            win[r][0] = a.x; win[r][1] = a.y; win[r][2] = bq.x; win[r][3] = bq.y;
        }

        const float* wp = &s_w[ci*144];
        #pragma unroll
        for (int r = 0; r < 3; ++r) {
            #pragma unroll
            for (int c = 0; c < 3; ++c) {
                const int k = r*3 + c;
                const float x0 = win[r][c], x1 = win[r][c + 1];
                #pragma unroll
                for (int og = 0; og < 4; ++og) {
                    float4 wv = *reinterpret_cast<const float4*>(&wp[k*16 + og*4]);
                    acc0[og*4+0] = fmaf(wv.x, x0, acc0[og*4+0]);
                    acc1[og*4+0] = fmaf(wv.x, x1, acc1[og*4+0]);
                    acc0[og*4+1] = fmaf(wv.y, x0, acc0[og*4+1]);
                    acc1[og*4+1] = fmaf(wv.y, x1, acc1[og*4+1]);
                    acc0[og*4+2] = fmaf(wv.z, x0, acc0[og*4+2]);
                    acc1[og*4+2] = fmaf(wv.z, x1, acc1[og*4+2]);
                    acc0[og*4+3] = fmaf(wv.w, x0, acc0[og*4+3]);
                    acc1[og*4+3] = fmaf(wv.w, x1, acc1[og*4+3]);
                }
            }
        }
        __syncthreads();
    }

    // ---- add bias (raw conv output, pre-BN)
    #pragma unroll
    for (int o = 0; o < 16; ++o) {
        float bv = bias[co0 + o];
        acc0[o] += bv; acc1[o] += bv;
    }

    const int y  = tileY + ty;
    const int x0 = tileX + 2*tx;

    if (WRITE_OUT) {
        #pragma unroll
        for (int o = 0; o < 16; ++o) {
            float2 v = make_float2(acc0[o], acc1[o]);
            *reinterpret_cast<float2*>(
                &out[(((size_t)b*COUT + co0 + o)*HH + y)*WW + x0]) = v;
        }
    }

    if (GATHER) {
        const int ny = nxy[b*64 + 62];
        const int nx = nxy[b*64 + 63];
        if (y == ny && (x0 == nx || x0 + 1 == nx)) {
            const bool first = (x0 == nx);
            #pragma unroll
            for (int o = 0; o < 16; ++o)
                gath[b*COUT + co0 + o] = first ? acc0[o] : acc1[o];
        }
    }

    // ---- block-level BN statistics -> one atomicAdd per channel
    const int lane = tid & 31, wid = tid >> 5;
    #pragma unroll
    for (int o = 0; o < 16; ++o) {
        float s  = acc0[o] + acc1[o];
        float ss = acc0[o]*acc0[o] + acc1[o]*acc1[o];
        #pragma unroll
        for (int off = 16; off; off >>= 1) {
            s  += __shfl_down_sync(0xffffffffu, s,  off);
            ss += __shfl_down_sync(0xffffffffu, ss, off);
        }
        if (lane == 0) { s_red[0][o][wid] = s; s_red[1][o][wid] = ss; }
    }
    __syncthreads();
    if (tid < 16) {
        float s = 0.f, ss = 0.f;
        #pragma unroll
        for (int k = 0; k < 8; ++k) { s += s_red[0][tid][k]; ss += s_red[1][tid][k]; }
        atomicAdd(&stats[co0 + tid],        s);
        atomicAdd(&stats[COUT + co0 + tid], ss);
    }
}

// ---------------- per-layer BN finalize ----------------
__global__ void finalize_aff(int C, int off,
                             const float* __restrict__ gamma,
                             const float* __restrict__ beta)
{
    int c = threadIdx.x;
    if (c < C) {
        const float n = (float)NPIX;
        float m = g_stats[off + c] / n;
        float v = g_stats[off + C + c] / n - m*m;
        float a = gamma[c] * rsqrtf(v + 1e-5f);
        g_aff[off + c]     = a;
        g_aff[off + C + c] = beta[c] - m*a;
    }
}

// ---------------- tail: image patches + encoded feature normalization ----------------
__global__ void tail_kernel(const float* __restrict__ image,
                            const int* __restrict__ axy,
                            const int* __restrict__ pxy,
                            const int* __restrict__ nxy,
                            float* __restrict__ out)
{
    int i = blockIdx.x*blockDim.x + threadIdx.x;
    if (i < 3528) {
        int which = i / 1176;
        int rem   = i % 1176;
        int b  = rem / 147;
        int r2 = rem % 147;
        int c  = r2 / 49;
        int p  = r2 % 49;
        int pi = p / 7, pj = p % 7;
        const int* xy = (which == 0) ? axy : (which == 1) ? pxy : nxy;
        int y0 = xy[b*64 + 62] - 3;
        int x0 = xy[b*64 + 63] - 3;
        out[i] = image[((b*3 + c)*HH + (y0 + pi))*WW + (x0 + pj)];
    } else if (i < 3528 + 1024) {
        int j = i - 3528;
        int c = j & 127;
        float v = fmaf(g_aff[192 + c], g_gath[j], g_aff[192 + 128 + c]);
        out[i] = (v > 0.f) ? v : 0.01f*v;
    }
}

// ---------------- launch ----------------
extern "C" void kernel_launch(void* const* d_in, const int* in_sizes, int n_in,
                              void* d_out, int out_size)
{
    const float* image = (const float*)d_in[0];
    const int*   axy   = (const int*)  d_in[1];
    const int*   pxy   = (const int*)  d_in[2];
    const int*   nxy   = (const int*)  d_in[3];
    const float* w1 = (const float*)d_in[4];
    const float* b1 = (const float*)d_in[5];
    const float* g1 = (const float*)d_in[6];
    const float* e1 = (const float*)d_in[7];
    const float* w2 = (const float*)d_in[8];
    const float* b2 = (const float*)d_in[9];
    const float* g2 = (const float*)d_in[10];
    const float* e2 = (const float*)d_in[11];
    const float* w3 = (const float*)d_in[12];
    const float* b3 = (const float*)d_in[13];
    const float* g3 = (const float*)d_in[14];
    const float* e3 = (const float*)d_in[15];
    float* outp = (float*)d_out;

    float *y1, *y2, *stats, *aff, *gath;
    cudaGetSymbolAddress((void**)&y1,    g_y1);
    cudaGetSymbolAddress((void**)&y2,    g_y2);
    cudaGetSymbolAddress((void**)&stats, g_stats);
    cudaGetSymbolAddress((void**)&aff,   g_aff);
    cudaGetSymbolAddress((void**)&gath,  g_gath);

    dim3 blk(256);

    zero_stats<<<2, 256>>>();

    conv3x3<3, 32, false, true, false><<<dim3(8,16,BB*2), blk>>>(
        image, w1, b1, nullptr, y1, stats + 0, nullptr, nullptr);
    finalize_aff<<<1, 32>>>(32, 0, g1, e1);

    conv3x3<32, 64, true, true, false><<<dim3(8,16,BB*4), blk>>>(
        y1, w2, b2, aff + 0, y2, stats + 64, nullptr, nullptr);
    finalize_aff<<<1, 64>>>(64, 64, g2, e2);

    conv3x3<64, 128, true, false, true><<<dim3(8,16,BB*8), blk>>>(
        y2, w3, b3, aff + 64, nullptr, stats + 192, gath, nxy);
    finalize_aff<<<1, 128>>>(128, 192, g3, e3);

    tail_kernel<<<(3528 + 1024 + 255)/256, 256>>>(image, axy, pxy, nxy, outp);
}

// round 3
// speedup vs baseline: 1.4914x; 1.1044x over previous
#include <cuda_runtime.h>

#define BB 8
#define HH 256
#define WW 256
#define NPIX (BB*HH*WW)

// ---------------- device scratch ----------------
__device__ float g_y1[BB*32*HH*WW];
__device__ float g_y2[(size_t)BB*64*HH*WW];
__device__ float g_stats[2*(32+64+128)];
__device__ float g_aff[2*(32+64+128)];
__device__ float g_gath[BB*128];

__global__ void zero_stats() {
    int i = blockIdx.x*blockDim.x + threadIdx.x;
    if (i < 448) g_stats[i] = 0.f;
}

// packed f32x2 helpers
__device__ __forceinline__ unsigned long long pack2(float lo, float hi) {
    unsigned long long r;
    asm("mov.b64 %0, {%1, %2};" : "=l"(r) : "f"(lo), "f"(hi));
    return r;
}
__device__ __forceinline__ void unpack2(unsigned long long v, float& lo, float& hi) {
    asm("mov.b64 {%0, %1}, %2;" : "=f"(lo), "=f"(hi) : "l"(v));
}
__device__ __forceinline__ void fma2(unsigned long long& d,
                                     unsigned long long a, unsigned long long b) {
    asm("fma.rn.f32x2 %0, %1, %2, %0;" : "+l"(d) : "l"(a), "l"(b));
}

// ---------------- fused conv3x3 (f32x2 packed over cout-pairs) ----------------
// 256 threads, output tile 32(W) x 16(H), 16 output channels / block.
// Thread: 2 adjacent pixels x 16 couts; accumulators packed as 8 cout-pairs per pixel.
template<int CIN, int COUT, bool APPLY_IN, bool WRITE_OUT, bool GATHER>
__global__ __launch_bounds__(256)
void conv3x3(const float* __restrict__ in,
             const float* __restrict__ w,      // [COUT,CIN,3,3]
             const float* __restrict__ bias,
             const float* __restrict__ aff,    // input affine: scale[CIN], shift[CIN]
             float* __restrict__ out,
             float* __restrict__ stats,
             float* __restrict__ gath,
             const int* __restrict__ nxy)
{
    __shared__ __align__(16) float s_w[CIN*9*16];      // [ci][k][o], couts consecutive
    __shared__ __align__(16) float s_in[2][18][36];
    __shared__ float s_red[2][16][8];

    const int tid = threadIdx.x;
    const int tx = tid & 15, ty = tid >> 4;
    const int tileX = blockIdx.x * 32, tileY = blockIdx.y * 16;
    const int ng  = COUT / 16;
    const int cog = blockIdx.z % ng;
    const int b   = blockIdx.z / ng;
    const int co0 = cog * 16;

    // preload all weights transposed to [ci][k][o]
    for (int e = tid; e < CIN*144; e += 256) {
        int ci  = e / 144;
        int rem = e - ci*144;
        int o   = rem / 9;
        int k   = rem - o*9;
        s_w[(ci*9 + k)*16 + o] = w[((co0 + o)*CIN + ci)*9 + k];
    }

    auto load_tile = [&](int ci, int buf) {
        const float* inp = in + ((size_t)(b*CIN + ci))*HH*WW;
        const float sA = APPLY_IN ? aff[ci]       : 0.f;
        const float sB = APPLY_IN ? aff[CIN + ci] : 0.f;
        #pragma unroll
        for (int e = tid; e < 18*34; e += 256) {
            int r = e / 34, c = e - r*34;
            int gy = tileY + r - 1, gx = tileX + c - 1;
            float v = 0.f;
            if ((unsigned)gy < (unsigned)HH && (unsigned)gx < (unsigned)WW) {
                v = inp[gy*WW + gx];
                if (APPLY_IN) {
                    v = fmaf(sA, v, sB);
                    v = (v > 0.f) ? v : 0.01f*v;
                }
            }
            s_in[buf][r][c] = v;
        }
    };

    // packed accumulators: 8 cout-pairs per pixel
    unsigned long long accP0[8], accP1[8];
    #pragma unroll
    for (int p = 0; p < 8; ++p) { accP0[p] = 0ull; accP1[p] = 0ull; }

    load_tile(0, 0);
    __syncthreads();

    for (int ci = 0; ci < CIN; ++ci) {
        const int buf = ci & 1;
        if (ci + 1 < CIN) load_tile(ci + 1, buf ^ 1);

        // window 3x4 (vector LDS.64, stride 36 keeps 8B alignment), then lane-dup packs
        unsigned long long wd[3][4];
        #pragma unroll
        for (int r = 0; r < 3; ++r) {
            float2 a = *reinterpret_cast<const float2*>(&s_in[buf][ty + r][2*tx]);
            float2 bq= *reinterpret_cast<const float2*>(&s_in[buf][ty + r][2*tx + 2]);
            wd[r][0] = pack2(a.x, a.x);
            wd[r][1] = pack2(a.y, a.y);
            wd[r][2] = pack2(bq.x, bq.x);
            wd[r][3] = pack2(bq.y, bq.y);
        }

        const float* wp = &s_w[ci*144];
        #pragma unroll
        for (int r = 0; r < 3; ++r) {
            #pragma unroll
            for (int c = 0; c < 3; ++c) {
                const int k = r*3 + c;
                #pragma unroll
                for (int q = 0; q < 4; ++q) {   // 4 x LDS.128 = 8 cout-pairs
                    // two packed weight pairs per float4
                    unsigned long long w2_[2];
                    asm("ld.shared.v2.b64 {%0, %1}, [%2];"
                        : "=l"(w2_[0]), "=l"(w2_[1])
                        : "r"((unsigned)__cvta_generic_to_shared(&wp[k*16 + q*4])));
                    fma2(accP0[2*q+0], w2_[0], wd[r][c]);
                    fma2(accP1[2*q+0], w2_[0], wd[r][c+1]);
                    fma2(accP0[2*q+1], w2_[1], wd[r][c]);
                    fma2(accP1[2*q+1], w2_[1], wd[r][c+1]);
                }
            }
        }
        __syncthreads();
    }

    // unpack + bias
    float acc0[16], acc1[16];
    #pragma unroll
    for (int p = 0; p < 8; ++p) {
        unpack2(accP0[p], acc0[2*p], acc0[2*p+1]);
        unpack2(accP1[p], acc1[2*p], acc1[2*p+1]);
    }
    #pragma unroll
    for (int o = 0; o < 16; ++o) {
        float bv = bias[co0 + o];
        acc0[o] += bv; acc1[o] += bv;
    }

    const int y  = tileY + ty;
    const int x0 = tileX + 2*tx;

    if (WRITE_OUT) {
        #pragma unroll
        for (int o = 0; o < 16; ++o) {
            float2 v = make_float2(acc0[o], acc1[o]);
            *reinterpret_cast<float2*>(
                &out[(((size_t)b*COUT + co0 + o)*HH + y)*WW + x0]) = v;
        }
    }

    if (GATHER) {
        const int ny = nxy[b*64 + 62];
        const int nx = nxy[b*64 + 63];
        if (y == ny && (x0 == nx || x0 + 1 == nx)) {
            const bool first = (x0 == nx);
            #pragma unroll
            for (int o = 0; o < 16; ++o)
                gath[b*COUT + co0 + o] = first ? acc0[o] : acc1[o];
        }
    }

    // BN stats: warp shuffle then one atomicAdd per channel
    const int lane = tid & 31, wid = tid >> 5;
    #pragma unroll
    for (int o = 0; o < 16; ++o) {
        float s  = acc0[o] + acc1[o];
        float ss = acc0[o]*acc0[o] + acc1[o]*acc1[o];
        #pragma unroll
        for (int off = 16; off; off >>= 1) {
            s  += __shfl_down_sync(0xffffffffu, s,  off);
            ss += __shfl_down_sync(0xffffffffu, ss, off);
        }
        if (lane == 0) { s_red[0][o][wid] = s; s_red[1][o][wid] = ss; }
    }
    __syncthreads();
    if (tid < 16) {
        float s = 0.f, ss = 0.f;
        #pragma unroll
        for (int k = 0; k < 8; ++k) { s += s_red[0][tid][k]; ss += s_red[1][tid][k]; }
        atomicAdd(&stats[co0 + tid],        s);
        atomicAdd(&stats[COUT + co0 + tid], ss);
    }
}

// ---------------- BN finalize ----------------
__global__ void finalize_aff(int C, int off,
                             const float* __restrict__ gamma,
                             const float* __restrict__ beta)
{
    int c = threadIdx.x;
    if (c < C) {
        const float n = (float)NPIX;
        float m = g_stats[off + c] / n;
        float v = g_stats[off + C + c] / n - m*m;
        float a = gamma[c] * rsqrtf(v + 1e-5f);
        g_aff[off + c]     = a;
        g_aff[off + C + c] = beta[c] - m*a;
    }
}

// ---------------- tail ----------------
__global__ void tail_kernel(const float* __restrict__ image,
                            const int* __restrict__ axy,
                            const int* __restrict__ pxy,
                            const int* __restrict__ nxy,
                            float* __restrict__ out)
{
    int i = blockIdx.x*blockDim.x + threadIdx.x;
    if (i < 3528) {
        int which = i / 1176;
        int rem   = i % 1176;
        int b  = rem / 147;
        int r2 = rem % 147;
        int c  = r2 / 49;
        int p  = r2 % 49;
        int pi = p / 7, pj = p % 7;
        const int* xy = (which == 0) ? axy : (which == 1) ? pxy : nxy;
        int y0 = xy[b*64 + 62] - 3;
        int x0 = xy[b*64 + 63] - 3;
        out[i] = image[((b*3 + c)*HH + (y0 + pi))*WW + (x0 + pj)];
    } else if (i < 3528 + 1024) {
        int j = i - 3528;
        int c = j & 127;
        float v = fmaf(g_aff[192 + c], g_gath[j], g_aff[192 + 128 + c]);
        out[i] = (v > 0.f) ? v : 0.01f*v;
    }
}

// ---------------- launch ----------------
extern "C" void kernel_launch(void* const* d_in, const int* in_sizes, int n_in,
                              void* d_out, int out_size)
{
    const float* image = (const float*)d_in[0];
    const int*   axy   = (const int*)  d_in[1];
    const int*   pxy   = (const int*)  d_in[2];
    const int*   nxy   = (const int*)  d_in[3];
    const float* w1 = (const float*)d_in[4];
    const float* b1 = (const float*)d_in[5];
    const float* g1 = (const float*)d_in[6];
    const float* e1 = (const float*)d_in[7];
    const float* w2 = (const float*)d_in[8];
    const float* b2 = (const float*)d_in[9];
    const float* g2 = (const float*)d_in[10];
    const float* e2 = (const float*)d_in[11];
    const float* w3 = (const float*)d_in[12];
    const float* b3 = (const float*)d_in[13];
    const float* g3 = (const float*)d_in[14];
    const float* e3 = (const float*)d_in[15];
    float* outp = (float*)d_out;

    float *y1, *y2, *stats, *aff, *gath;
    cudaGetSymbolAddress((void**)&y1,    g_y1);
    cudaGetSymbolAddress((void**)&y2,    g_y2);
    cudaGetSymbolAddress((void**)&stats, g_stats);
    cudaGetSymbolAddress((void**)&aff,   g_aff);
    cudaGetSymbolAddress((void**)&gath,  g_gath);

    dim3 blk(256);

    zero_stats<<<2, 256>>>();

    conv3x3<3, 32, false, true, false><<<dim3(8,16,BB*2), blk>>>(
        image, w1, b1, nullptr, y1, stats + 0, nullptr, nullptr);
    finalize_aff<<<1, 32>>>(32, 0, g1, e1);

    conv3x3<32, 64, true, true, false><<<dim3(8,16,BB*4), blk>>>(
        y1, w2, b2, aff + 0, y2, stats + 64, nullptr, nullptr);
    finalize_aff<<<1, 64>>>(64, 64, g2, e2);

    conv3x3<64, 128, true, false, true><<<dim3(8,16,BB*8), blk>>>(
        y2, w3, b3, aff + 64, nullptr, stats + 192, gath, nxy);
    finalize_aff<<<1, 128>>>(128, 192, g3, e3);

    tail_kernel<<<(3528 + 1024 + 255)/256, 256>>>(image, axy, pxy, nxy, outp);
}